// round 16
// baseline (speedup 1.0000x reference)
#include <cuda_runtime.h>

#define THETA 0.5f
#define EPS   1e-5f

// finest-level (p=2) per-patch stats: (sum, sumsq). 512 planes x 16 patches.
__device__ float2 g_stats[512 * 16];

__device__ __forceinline__ float fast_tanh(float x) {
    float y;
    asm("tanh.approx.f32 %0, %1;" : "=f"(y) : "f"(x));
    return y;
}

struct f8 { float4 a, b; };

// 32-byte load, pinned in L2 (lowest eviction priority): survives the apply
// kernel's write-allocation stream. sm_103 requires .v4.b64 for evict hints.
__device__ __forceinline__ f8 ldg_pin(const void* p) {
    unsigned long long u0, u1, u2, u3;
    asm("ld.global.L2::evict_last.v4.b64 {%0,%1,%2,%3}, [%4];"
        : "=l"(u0), "=l"(u1), "=l"(u2), "=l"(u3) : "l"(p));
    f8 r;
    r.a.x = __uint_as_float((unsigned)u0); r.a.y = __uint_as_float((unsigned)(u0 >> 32));
    r.a.z = __uint_as_float((unsigned)u1); r.a.w = __uint_as_float((unsigned)(u1 >> 32));
    r.b.x = __uint_as_float((unsigned)u2); r.b.y = __uint_as_float((unsigned)(u2 >> 32));
    r.b.z = __uint_as_float((unsigned)u3); r.b.w = __uint_as_float((unsigned)(u3 >> 32));
    return r;
}
// 32-byte consume-once load: hit then demote, freeing room for the write stream.
__device__ __forceinline__ f8 ldg_consume(const void* p) {
    unsigned long long u0, u1, u2, u3;
    asm("ld.global.L2::evict_first.v4.b64 {%0,%1,%2,%3}, [%4];"
        : "=l"(u0), "=l"(u1), "=l"(u2), "=l"(u3) : "l"(p));
    f8 r;
    r.a.x = __uint_as_float((unsigned)u0); r.a.y = __uint_as_float((unsigned)(u0 >> 32));
    r.a.z = __uint_as_float((unsigned)u1); r.a.w = __uint_as_float((unsigned)(u1 >> 32));
    r.b.x = __uint_as_float((unsigned)u2); r.b.y = __uint_as_float((unsigned)(u2 >> 32));
    r.b.z = __uint_as_float((unsigned)u3); r.b.w = __uint_as_float((unsigned)(u3 >> 32));
    return r;
}

// ---------- Kernel 1: per-patch stats (read-only streaming) ----------
// One CTA per 64x64 patch. 256 threads; thread t owns an 8-float strip:
// col = (t&7)*8, rows (t>>3) and (t>>3)+32 -> 2 x 32B loads = 16 elements.
__global__ __launch_bounds__(256) void pmfm_stats(const float* __restrict__ x) {
    const int bc = blockIdx.y;           // plane (b*C + c), forward order
    const int pi = blockIdx.x;           // 0..15 finest patch
    const float* base = x + (size_t)bc * 65536
                          + (size_t)(pi >> 2) * (64 * 256)
                          + (pi & 3) * 64;
    const int t    = threadIdx.x;
    const int col  = (t & 7) << 3;       // float col (32B aligned)
    const int row0 = t >> 3;             // 0..31

    const f8 v0 = ldg_pin(base + (size_t)row0 * 256 + col);
    const f8 v1 = ldg_pin(base + (size_t)(row0 + 32) * 256 + col);

    float s = 0.f, ss = 0.f;
#define PMFM_ACC(q) \
    s  += ((q).x + (q).y) + ((q).z + (q).w); \
    ss += (q).x * (q).x + (q).y * (q).y + (q).z * (q).z + (q).w * (q).w;
    PMFM_ACC(v0.a) PMFM_ACC(v0.b) PMFM_ACC(v1.a) PMFM_ACC(v1.b)
#undef PMFM_ACC
#pragma unroll
    for (int o = 16; o > 0; o >>= 1) {
        s  += __shfl_xor_sync(0xffffffffu, s,  o);
        ss += __shfl_xor_sync(0xffffffffu, ss, o);
    }
    __shared__ float2 red[8];
    if ((t & 31) == 0) red[t >> 5] = make_float2(s, ss);
    __syncthreads();
    if (t == 0) {
        float S = 0.f, SS = 0.f;
#pragma unroll
        for (int i = 0; i < 8; ++i) { S += red[i].x; SS += red[i].y; }
        g_stats[bc * 16 + pi] = make_float2(S, SS);
    }
}

// ---------- Kernel 2: gate + blend (streaming, REVERSE plane order) ----------
// Planes visited newest-first so reads hit x pinned in L2 by kernel 1.
__global__ __launch_bounds__(256) void pmfm_apply(const float* __restrict__ x,
                                                  const float* __restrict__ lw,
                                                  float* __restrict__ out) {
    const int bc = (int)(gridDim.y - 1 - blockIdx.y);   // reverse order
    const int pi = blockIdx.x;

    __shared__ float2 st[16];
    if (threadIdx.x < 16) st[threadIdx.x] = g_stats[bc * 16 + threadIdx.x];
    __syncthreads();

    const int pr = pi >> 2, pc = pi & 3;

    const float2 f2 = st[pi];                      // level 2: this patch
    float s1 = 0.f, q1 = 0.f;                      // level 1: 2x2 quadrant
    {
        const int qr = pr & ~1, qc = pc & ~1;
#pragma unroll
        for (int dr = 0; dr < 2; ++dr)
#pragma unroll
            for (int dc = 0; dc < 2; ++dc) {
                const float2 v = st[(qr + dr) * 4 + (qc + dc)];
                s1 += v.x; q1 += v.y;
            }
    }
    float s0 = 0.f, q0 = 0.f;                      // level 0: whole plane
#pragma unroll
    for (int i = 0; i < 16; ++i) { s0 += st[i].x; q0 += st[i].y; }

    const float iN2 = 1.f / 4096.f, iN1 = 1.f / 16384.f, iN0 = 1.f / 65536.f;
    const float mu2 = f2.x * iN2; const float v2 = fmaxf(f2.y * iN2 - mu2 * mu2, 0.f);
    const float mu1 = s1  * iN1; const float v1 = fmaxf(q1  * iN1 - mu1 * mu1, 0.f);
    const float mu0 = s0  * iN0; const float v0 = fmaxf(q0  * iN0 - mu0 * mu0, 0.f);

    // sigmoid(z) = 0.5 + 0.5*tanh(z/2); arg = x*a + b, a = 0.5*rsig, b = -mu*a
    const float a2 = 0.5f * rsqrtf(v2 + EPS), b2 = -mu2 * a2;
    const float a1 = 0.5f * rsqrtf(v1 + EPS), b1 = -mu1 * a1;
    const float a0 = 0.5f * rsqrtf(v0 + EPS), b0 = -mu0 * a0;

    // softmax(level_weights); lw[0] pairs with p=2 (finest), lw[2] with p=0
    const float w0 = __ldg(lw + 0), w1 = __ldg(lw + 1), w2 = __ldg(lw + 2);
    const float m  = fmaxf(w0, fmaxf(w1, w2));
    const float e0 = __expf(w0 - m), e1 = __expf(w1 - m), e2 = __expf(w2 - m);
    const float c  = (1.f - THETA) * 0.5f / (e0 + e1 + e2);
    const float cf = c * e0, cm = c * e1, cg = c * e2;
    const float basew = THETA + (1.f - THETA) * 0.5f;

    const size_t off = (size_t)bc * 65536 + (size_t)pr * (64 * 256) + pc * 64;
    const float* xin = x + off;
    float* o = out + off;
    const int t    = threadIdx.x;
    const int col  = (t & 7) << 3;       // float col (32B aligned)
    const int row0 = t >> 3;             // 0..31

    // batched 32B loads first (MLP=2x32B), then compute+store
    const f8 v0_ = ldg_consume(xin + (size_t)row0 * 256 + col);
    const f8 v1_ = ldg_consume(xin + (size_t)(row0 + 32) * 256 + col);

#define PMFM_DO(res, q)                                                   \
    {                                                                     \
        const float xx = (q);                                             \
        const float tf = fast_tanh(fmaf(xx, a2, b2));                     \
        const float tm = fast_tanh(fmaf(xx, a1, b1));                     \
        const float tg = fast_tanh(fmaf(xx, a0, b0));                     \
        (res) = xx * fmaf(cf, tf, fmaf(cm, tm, fmaf(cg, tg, basew)));     \
    }
#define PMFM_GATE4(res, q)                                                \
    PMFM_DO((res).x, (q).x) PMFM_DO((res).y, (q).y)                       \
    PMFM_DO((res).z, (q).z) PMFM_DO((res).w, (q).w)

    float4 r;
    PMFM_GATE4(r, v0_.a);
    __stcs(reinterpret_cast<float4*>(o + (size_t)row0 * 256 + col), r);
    PMFM_GATE4(r, v0_.b);
    __stcs(reinterpret_cast<float4*>(o + (size_t)row0 * 256 + col + 4), r);
    PMFM_GATE4(r, v1_.a);
    __stcs(reinterpret_cast<float4*>(o + (size_t)(row0 + 32) * 256 + col), r);
    PMFM_GATE4(r, v1_.b);
    __stcs(reinterpret_cast<float4*>(o + (size_t)(row0 + 32) * 256 + col + 4), r);
#undef PMFM_GATE4
#undef PMFM_DO
}

extern "C" void kernel_launch(void* const* d_in, const int* in_sizes, int n_in,
                              void* d_out, int out_size) {
    const float* x;
    const float* lw;
    long nx;
    if (in_sizes[0] >= in_sizes[1]) {
        x = (const float*)d_in[0]; lw = (const float*)d_in[1]; nx = in_sizes[0];
    } else {
        x = (const float*)d_in[1]; lw = (const float*)d_in[0]; nx = in_sizes[1];
    }
    const int nplanes = (int)(nx / 65536);   // B*C = 512 planes of 256x256
    dim3 grid(16, nplanes);
    pmfm_stats<<<grid, 256>>>(x);
    pmfm_apply<<<grid, 256>>>(x, lw, (float*)d_out);
}

// round 17
// speedup vs baseline: 1.0694x; 1.0694x over previous
#include <cuda_runtime.h>
#include <cooperative_groups.h>
namespace cg = cooperative_groups;

#define THETA 0.5f
#define EPS   1e-5f

__device__ __forceinline__ float fast_tanh(float x) {
    float y;
    asm("tanh.approx.f32 %0, %1;" : "=f"(y) : "f"(x));
    return y;
}

// Cluster of 2 CTAs owns TWO adjacent planes A=2j, B=2j+1; CTA rank r owns
// rows [128r, 128r+128) of both. 256 threads = 8 warps; warp w = 64x64 patch.
// Stage 1: stats(A) (8-deep MLP) + exchange; stage-2's first B chunk is
// prefetched BEFORE the sync so the barrier hides under DRAM reads.
// Stage 2: B stats reads (DRAM) interleaved with A gate+store (distance-1
// rotate on the B buffer). Stage 3: B re-read chunks primed BEFORE the second
// sync; exchange; gate+store B (reverse, L2-hot, distance-2 buffer).
__global__ __launch_bounds__(256, 4) __cluster_dims__(2, 1, 1)
void pmfm_fused(const float* __restrict__ x,
                const float* __restrict__ lw,
                float* __restrict__ out) {
    cg::cluster_group cluster = cg::this_cluster();
    const unsigned rank = cluster.block_rank();

    const int cid  = blockIdx.x >> 1;     // cluster id -> planes 2*cid, 2*cid+1
    const int t    = threadIdx.x;
    const int w    = t >> 5;              // warp 0..7 = local patch
    const int lane = t & 31;
    const int prow = (int)rank * 2 + (w >> 2);
    const int pcol = w & 3;

    const size_t planeA = (size_t)(2 * cid) * 65536;
    const int colf  = pcol * 64 + (lane & 15) * 4;
    const int rbase = prow * 64 + (lane >> 4);      // start row (stride 2)
    const size_t off = (size_t)rbase * 256 + colf;

    const float4* pinA = reinterpret_cast<const float4*>(x + planeA + off);
    const float4* pinB = reinterpret_cast<const float4*>(x + planeA + 65536 + off);
    float4*       poA  = reinterpret_cast<float4*>(out + planeA + off);
    float4*       poB  = reinterpret_cast<float4*>(out + planeA + 65536 + off);

    __shared__ float2 st[8];        // per-patch stats (reused for A then B)
    __shared__ float2 sh_half;      // this CTA's half-plane total (A then B)

    // softmax(level_weights) — constant for both planes
    const float w0 = __ldg(lw + 0), w1 = __ldg(lw + 1), w2 = __ldg(lw + 2);
    const float mmx = fmaxf(w0, fmaxf(w1, w2));
    const float ew0 = __expf(w0 - mmx), ew1 = __expf(w1 - mmx), ew2 = __expf(w2 - mmx);
    const float cc = (1.f - THETA) * 0.5f / (ew0 + ew1 + ew2);
    const float cf = cc * ew0, cm = cc * ew1, cg_ = cc * ew2;
    const float basew = THETA + (1.f - THETA) * 0.5f;
    const float iN2 = 1.f / 4096.f, iN1 = 1.f / 16384.f, iN0 = 1.f / 65536.f;

#define PMFM_SUMSQ(v, S, Q)                                                  \
    S += ((v).x + (v).y) + ((v).z + (v).w);                                  \
    Q += (v).x * (v).x + (v).y * (v).y + (v).z * (v).z + (v).w * (v).w;

    // ====== Stage 1: stats over plane A (8-deep load batches) ======
    float s = 0.f, q = 0.f, s2 = 0.f, q2 = 0.f;
#pragma unroll
    for (int c = 0; c < 4; ++c) {
        float4 v[8];
#pragma unroll
        for (int j = 0; j < 8; ++j) v[j] = pinA[(size_t)(8 * c + j) * 128];
#pragma unroll
        for (int j = 0; j < 8; j += 2) {
            PMFM_SUMSQ(v[j],     s,  q)
            PMFM_SUMSQ(v[j + 1], s2, q2)
        }
    }
    s += s2; q += q2;
#pragma unroll
    for (int o = 16; o > 0; o >>= 1) {
        s += __shfl_xor_sync(0xffffffffu, s, o);
        q += __shfl_xor_sync(0xffffffffu, q, o);
    }
    if (lane == 0) st[w] = make_float2(s, q);
    __syncthreads();
    if (t < 8) {
        float2 v = st[t];
        float hs = v.x, hq = v.y;
#pragma unroll
        for (int o = 4; o > 0; o >>= 1) {
            hs += __shfl_xor_sync(0x000000ffu, hs, o, 8);
            hq += __shfl_xor_sync(0x000000ffu, hq, o, 8);
        }
        if (t == 0) sh_half = make_float2(hs, hq);
    }
    __syncthreads();

    // Prime stage-2: first B chunk (DRAM) issued BEFORE the cluster barrier,
    // so the sync + exchange + coeff latency hides under these loads.
    float4 nb0 = pinB[(size_t)0 * 128];
    float4 nb1 = pinB[(size_t)1 * 128];

    cluster.sync();

    // exchange A: pull peer's half-plane total
    float phs, phq;
    {
        float2 ph = make_float2(0.f, 0.f);
        if (lane == 0)
            ph = *(const float2*)cluster.map_shared_rank((void*)&sh_half, rank ^ 1u);
        phs = __shfl_sync(0xffffffffu, ph.x, 0);
        phq = __shfl_sync(0xffffffffu, ph.y, 0);
    }
    // coefficients for A
    float a2c, b2c, a1c, b1c, a0c, b0c;
    {
        const float2 f2 = st[w];
        float s1 = 0.f, q1 = 0.f;
        const int qc = pcol & ~1;
#pragma unroll
        for (int dr = 0; dr < 2; ++dr)
#pragma unroll
            for (int dc = 0; dc < 2; ++dc) {
                const float2 v = st[dr * 4 + (qc + dc)];
                s1 += v.x; q1 += v.y;
            }
        const float s0 = sh_half.x + phs, q0 = sh_half.y + phq;
        const float mu2 = f2.x * iN2; const float v2 = fmaxf(f2.y * iN2 - mu2 * mu2, 0.f);
        const float mu1 = s1  * iN1; const float v1 = fmaxf(q1  * iN1 - mu1 * mu1, 0.f);
        const float mu0 = s0  * iN0; const float v0 = fmaxf(q0  * iN0 - mu0 * mu0, 0.f);
        a2c = 0.5f * rsqrtf(v2 + EPS); b2c = -mu2 * a2c;
        a1c = 0.5f * rsqrtf(v1 + EPS); b1c = -mu1 * a1c;
        a0c = 0.5f * rsqrtf(v0 + EPS); b0c = -mu0 * a0c;
    }

#define PMFM_GATE(res, vin)                                                    \
    {                                                                          \
        const float4 _v = (vin);                                               \
        float* _r = (float*)&(res);                                            \
        const float* _x = (const float*)&_v;                                   \
        _Pragma("unroll")                                                      \
        for (int _k = 0; _k < 4; ++_k) {                                       \
            const float xx = _x[_k];                                           \
            const float tf = fast_tanh(fmaf(xx, a2c, b2c));                    \
            const float tm = fast_tanh(fmaf(xx, a1c, b1c));                    \
            const float tg = fast_tanh(fmaf(xx, a0c, b0c));                    \
            _r[_k] = xx * fmaf(cf, tf, fmaf(cm, tm, fmaf(cg_, tg, basew)));    \
        }                                                                      \
    }

    // ===== Stage 2: B stats reads (distance-1 rotate) + A gate+store =====
    float bs = 0.f, bq = 0.f, bs2 = 0.f, bq2 = 0.f;
#pragma unroll
    for (int c = 0; c < 16; ++c) {
        const float4 b0 = nb0, b1 = nb1;
        if (c < 15) {
            nb0 = pinB[(size_t)(2 * (c + 1) + 0) * 128];
            nb1 = pinB[(size_t)(2 * (c + 1) + 1) * 128];
        }
        const float4 va0 = __ldcs(&pinA[(size_t)(2 * (15 - c) + 0) * 128]);
        const float4 va1 = __ldcs(&pinA[(size_t)(2 * (15 - c) + 1) * 128]);
        PMFM_SUMSQ(b0, bs, bq)  PMFM_SUMSQ(b1, bs2, bq2)
        float4 r0, r1;
        PMFM_GATE(r0, va0);
        PMFM_GATE(r1, va1);
        __stcs(&poA[(size_t)(2 * (15 - c) + 0) * 128], r0);
        __stcs(&poA[(size_t)(2 * (15 - c) + 1) * 128], r1);
    }

    // ================= Stage 3: B stats exchange + apply =================
    bs += bs2; bq += bq2;
#pragma unroll
    for (int o = 16; o > 0; o >>= 1) {
        bs += __shfl_xor_sync(0xffffffffu, bs, o);
        bq += __shfl_xor_sync(0xffffffffu, bq, o);
    }
    __syncthreads();               // everyone done reading st[] A-values
    if (lane == 0) st[w] = make_float2(bs, bq);
    __syncthreads();
    if (t < 8) {
        float2 v = st[t];
        float hs = v.x, hq = v.y;
#pragma unroll
        for (int o = 4; o > 0; o >>= 1) {
            hs += __shfl_xor_sync(0x000000ffu, hs, o, 8);
            hq += __shfl_xor_sync(0x000000ffu, hq, o, 8);
        }
        if (t == 0) sh_half = make_float2(hs, hq);
    }
    __syncthreads();

    // Prime stage-3: B re-read chunks 15, 14 (L2-hot) BEFORE the second sync.
    float4 buf[2][2];
    buf[1][0] = __ldcs(&pinB[(size_t)(2 * 15 + 0) * 128]);
    buf[1][1] = __ldcs(&pinB[(size_t)(2 * 15 + 1) * 128]);
    buf[0][0] = __ldcs(&pinB[(size_t)(2 * 14 + 0) * 128]);
    buf[0][1] = __ldcs(&pinB[(size_t)(2 * 14 + 1) * 128]);

    cluster.sync();
    {
        float2 ph = make_float2(0.f, 0.f);
        if (lane == 0)
            ph = *(const float2*)cluster.map_shared_rank((void*)&sh_half, rank ^ 1u);
        phs = __shfl_sync(0xffffffffu, ph.x, 0);   // forces pull complete
        phq = __shfl_sync(0xffffffffu, ph.y, 0);
    }
    // Early arrive: done reading peer smem; matching wait at kernel end.
    asm volatile("barrier.cluster.arrive.aligned;" ::: "memory");
    {
        const float2 f2 = st[w];
        float s1 = 0.f, q1 = 0.f;
        const int qc = pcol & ~1;
#pragma unroll
        for (int dr = 0; dr < 2; ++dr)
#pragma unroll
            for (int dc = 0; dc < 2; ++dc) {
                const float2 v = st[dr * 4 + (qc + dc)];
                s1 += v.x; q1 += v.y;
            }
        const float s0 = sh_half.x + phs, q0 = sh_half.y + phq;
        const float mu2 = f2.x * iN2; const float v2 = fmaxf(f2.y * iN2 - mu2 * mu2, 0.f);
        const float mu1 = s1  * iN1; const float v1 = fmaxf(q1  * iN1 - mu1 * mu1, 0.f);
        const float mu0 = s0  * iN0; const float v0 = fmaxf(q0  * iN0 - mu0 * mu0, 0.f);
        a2c = 0.5f * rsqrtf(v2 + EPS); b2c = -mu2 * a2c;
        a1c = 0.5f * rsqrtf(v1 + EPS); b1c = -mu1 * a1c;
        a0c = 0.5f * rsqrtf(v0 + EPS); b0c = -mu0 * a0c;
    }
    // apply B: reverse-order L2-hot re-read, distance-2 buffer
#pragma unroll
    for (int c = 15; c >= 0; --c) {
        const float4 cur0 = buf[c & 1][0];
        const float4 cur1 = buf[c & 1][1];
        if (c >= 2) {
            buf[c & 1][0] = __ldcs(&pinB[(size_t)(2 * (c - 2) + 0) * 128]);
            buf[c & 1][1] = __ldcs(&pinB[(size_t)(2 * (c - 2) + 1) * 128]);
        }
        float4 r0, r1;
        PMFM_GATE(r0, cur0);
        PMFM_GATE(r1, cur1);
        __stcs(&poB[(size_t)(2 * c + 0) * 128], r0);
        __stcs(&poB[(size_t)(2 * c + 1) * 128], r1);
    }
#undef PMFM_GATE
#undef PMFM_SUMSQ

    // No CTA exits while its peer might still read sh_half.
    asm volatile("barrier.cluster.wait.aligned;" ::: "memory");
}

extern "C" void kernel_launch(void* const* d_in, const int* in_sizes, int n_in,
                              void* d_out, int out_size) {
    const float* x;
    const float* lw;
    long nx;
    if (in_sizes[0] >= in_sizes[1]) {
        x = (const float*)d_in[0]; lw = (const float*)d_in[1]; nx = in_sizes[0];
    } else {
        x = (const float*)d_in[1]; lw = (const float*)d_in[0]; nx = in_sizes[1];
    }
    const int nplanes = (int)(nx / 65536);   // B*C = 512 planes of 256x256
    pmfm_fused<<<nplanes, 256>>>(x, lw, (float*)d_out);   // 2 planes / cluster
}